// round 15
// baseline (speedup 1.0000x reference)
#include <cuda_runtime.h>
#include <math.h>

#define NB 4
#define NS 256
#define NV 1280
#define NH 128
#define EPSV 1e-5f
#define NROWS (NB*NS)        // 1024
#define SPLITS 10
#define KCHUNK (NV/SPLITS)   // 128

// ---------------- scratch (no allocation allowed) ----------------
__device__ float g_q [NB*NS*NH];
__device__ float g_kT[NB*NH*NS];
__device__ float g_Xn[NB*NS*NV];
__device__ float g_h [NB*NS*NH];
__device__ float g_X2[NB*NS*NV];
__device__ float g_Y [NB*NS*NV];               // pre-LN attention output
__device__ float g_S [NB*NS*NS];               // softmax probabilities
__device__ float g_P [SPLITS * NROWS * 256];   // split-K partials (max N=256)

// single-MUFU tanh (MUFU.TANH)
__device__ __forceinline__ float tanh_fast(float x) {
    float y;
    asm("tanh.approx.f32 %0, %1;" : "=f"(y) : "f"(x));
    return y;
}

// =====================================================================
// Shared GEMM core: BM=128, BN=64, BK=16, 256 threads, 8x4 per thread.
// Double-buffered smem, one __syncthreads per k-tile, reg prefetch.
//   As layout: [2][16][132] (k-major, padded), Bs: [2][16][68].
//   Aptr: thread's A load ptr (rows a_m and a_m+64 via +64*lda), +16/tile.
//   Bptr: thread's B load ptr, +16*ldb per tile.
// =====================================================================
#define AS_STR 132
#define BS_STR 68
#define SM_A (16*AS_STR)
#define SM_B (16*BS_STR)

__device__ __forceinline__ void gemm_body(
    const float* __restrict__ Aptr, int lda,
    const float* __restrict__ Bptr, int ldb,
    int ntiles, float (&acc)[8][4],
    float* __restrict__ As, float* __restrict__ Bs)
{
    const int tid = threadIdx.x;
    const int tx = tid & 15;        // n group (x4)
    const int ty = tid >> 4;        // m group (x8)
    const int a_kc = tid & 3;       // k group of 4
    const int a_m  = tid >> 2;      // 0..63

    float4 ra0 = *(const float4*)Aptr;
    float4 ra1 = *(const float4*)(Aptr + (size_t)64 * lda);
    float4 rb  = *(const float4*)Bptr;

    for (int t = 0; t < ntiles; t++) {
        const int buf = t & 1;
        float* Ab = As + buf * SM_A;
        float* Bb = Bs + buf * SM_B;
        Ab[(a_kc*4+0)*AS_STR + a_m] = ra0.x;
        Ab[(a_kc*4+1)*AS_STR + a_m] = ra0.y;
        Ab[(a_kc*4+2)*AS_STR + a_m] = ra0.z;
        Ab[(a_kc*4+3)*AS_STR + a_m] = ra0.w;
        Ab[(a_kc*4+0)*AS_STR + a_m + 64] = ra1.x;
        Ab[(a_kc*4+1)*AS_STR + a_m + 64] = ra1.y;
        Ab[(a_kc*4+2)*AS_STR + a_m + 64] = ra1.z;
        Ab[(a_kc*4+3)*AS_STR + a_m + 64] = ra1.w;
        *(float4*)&Bb[(tid >> 4)*BS_STR + (tid & 15)*4] = rb;
        __syncthreads();

        if (t + 1 < ntiles) {
            const float* An = Aptr + (t+1)*16;
            const float* Bn = Bptr + (size_t)(t+1)*16*ldb;
            ra0 = *(const float4*)An;
            ra1 = *(const float4*)(An + (size_t)64 * lda);
            rb  = *(const float4*)Bn;
        }

#pragma unroll
        for (int kk = 0; kk < 16; kk++) {
            float4 a0 = *(const float4*)&Ab[kk*AS_STR + ty*8];
            float4 a1 = *(const float4*)&Ab[kk*AS_STR + ty*8 + 4];
            float4 bv = *(const float4*)&Bb[kk*BS_STR + tx*4];
            float am[8] = {a0.x,a0.y,a0.z,a0.w,a1.x,a1.y,a1.z,a1.w};
#pragma unroll
            for (int i = 0; i < 8; i++) {
                acc[i][0] += am[i]*bv.x; acc[i][1] += am[i]*bv.y;
                acc[i][2] += am[i]*bv.z; acc[i][3] += am[i]*bv.w;
            }
        }
    }
}

// ---------------- split-K SGEMM: P[s] = A[:, sK:(s+1)K] @ W_chunk ----------------
// NW=2: cols 0..127 from W0, 128..255 from W1 (fused q/k projection).
template<int NW>
__global__ __launch_bounds__(256, 2)
void gemm_splitk(const float* __restrict__ A,
                 const float* __restrict__ W0,
                 const float* __restrict__ W1,
                 float* __restrict__ P) {
    __shared__ __align__(16) float As[2*SM_A];
    __shared__ __align__(16) float Bs[2*SM_B];
    const int tid = threadIdx.x;
    const int tx = tid & 15;
    const int ty = tid >> 4;
    const int m0 = blockIdx.x * 128;
    const int n0 = blockIdx.y * 64;
    const int s  = blockIdx.z;
    const int kbase = s * KCHUNK;
    const int N = NW * 128;

    const float* W = (NW == 2 && n0 >= 128) ? W1 : W0;
    const int nw0  = (NW == 2) ? (n0 & 127) : n0;

    const float* Aptr = A + (size_t)(m0 + (tid >> 2)) * NV + kbase + (tid & 3) * 4;
    const float* Bptr = W + (size_t)(kbase + (tid >> 4)) * 128 + nw0 + (tid & 15) * 4;

    float acc[8][4] = {};
    gemm_body(Aptr, NV, Bptr, 128, KCHUNK/16, acc, As, Bs);

#pragma unroll
    for (int i = 0; i < 8; i++) {
        int m = m0 + ty*8 + i;
        float4 v = make_float4(acc[i][0], acc[i][1], acc[i][2], acc[i][3]);
        *(float4*)&P[((size_t)s * NROWS + m) * N + n0 + tx*4] = v;
    }
}

// ---- epilogue qk: sum splits; n<128 -> q, n>=128 -> kT (transposed) ----
__global__ void epi_qk(const float* __restrict__ P, float* __restrict__ q,
                       float* __restrict__ kT) {
    int gid = blockIdx.x * 256 + threadIdx.x;
    int m = gid >> 6, n = (gid & 63) * 4;
    float4 v = make_float4(0.f, 0.f, 0.f, 0.f);
#pragma unroll
    for (int s = 0; s < SPLITS; s++) {
        float4 p = *(const float4*)&P[((size_t)s * NROWS + m) * 256 + n];
        v.x += p.x; v.y += p.y; v.z += p.z; v.w += p.w;
    }
    if (n < 128) {
        *(float4*)&q[(size_t)m * NH + n] = v;
    } else {
        int b = m >> 8, col = m & 255;
        int h = n - 128;
        kT[((size_t)(b*NH + h+0)) * NS + col] = v.x;
        kT[((size_t)(b*NH + h+1)) * NS + col] = v.y;
        kT[((size_t)(b*NH + h+2)) * NS + col] = v.z;
        kT[((size_t)(b*NH + h+3)) * NS + col] = v.w;
    }
}

// ---- epilogue fc1: sum splits + bias + relu ----
__global__ void epi_bias_relu(const float* __restrict__ P, const float* __restrict__ bias,
                              float* __restrict__ outp) {
    int gid = blockIdx.x * 256 + threadIdx.x;
    int m = gid >> 5, n = (gid & 31) * 4;
    float4 v = *(const float4*)&bias[n];
#pragma unroll
    for (int s = 0; s < SPLITS; s++) {
        float4 p = *(const float4*)&P[((size_t)s * NROWS + m) * 128 + n];
        v.x += p.x; v.y += p.y; v.z += p.z; v.w += p.w;
    }
    v.x = fmaxf(v.x, 0.f); v.y = fmaxf(v.y, 0.f);
    v.z = fmaxf(v.z, 0.f); v.w = fmaxf(v.w, 0.f);
    *(float4*)&outp[(size_t)m * NH + n] = v;
}

// ---- epilogue k4: sum splits + transposed store ----
__global__ void epi_ktrans(const float* __restrict__ P, float* __restrict__ kT) {
    int gid = blockIdx.x * 256 + threadIdx.x;
    int m = gid >> 5, n = (gid & 31) * 4;
    float4 v = make_float4(0.f, 0.f, 0.f, 0.f);
#pragma unroll
    for (int s = 0; s < SPLITS; s++) {
        float4 p = *(const float4*)&P[((size_t)s * NROWS + m) * 128 + n];
        v.x += p.x; v.y += p.y; v.z += p.z; v.w += p.w;
    }
    int b = m >> 8, col = m & 255;
    kT[((size_t)(b*NH + n+0)) * NS + col] = v.x;
    kT[((size_t)(b*NH + n+1)) * NS + col] = v.y;
    kT[((size_t)(b*NH + n+2)) * NS + col] = v.z;
    kT[((size_t)(b*NH + n+3)) * NS + col] = v.w;
}

// ---------------- scores + softmax -> S[b,i,j] ----------------
__global__ void score_softmax(const float* __restrict__ q, const float* __restrict__ kT,
                              const float* __restrict__ wv, float* __restrict__ S) {
    const int G = 8;
    __shared__ float sq[G][NH];
    __shared__ float swv[NH];
    __shared__ float sp[G][NS];

    const int tid = threadIdx.x;
    const int b  = blockIdx.x >> 5;
    const int i0 = (blockIdx.x & 31) * G;
    const int wid = tid >> 5, lane = tid & 31;

    if (tid < NH) swv[tid] = wv[tid];
    for (int t = tid; t < G*NH; t += 256) {
        int r = t >> 7, h = t & 127;
        sq[r][h] = q[(size_t)(b*NS + i0 + r) * NH + h];
    }
    __syncthreads();

    {
        float sc[G];
#pragma unroll
        for (int r = 0; r < G; r++) sc[r] = 0.f;
        const float* kp = kT + (size_t)(b*NH) * NS + tid;
        for (int h = 0; h < NH; h++) {
            float kv = kp[(size_t)h * NS];
            float w  = swv[h];
#pragma unroll
            for (int r = 0; r < G; r++) sc[r] += w * tanh_fast(sq[r][h] + kv);
        }
#pragma unroll
        for (int r = 0; r < G; r++) sp[r][tid] = sc[r];
    }
    __syncthreads();

    {
        float mx = -1e30f;
        for (int jj = lane; jj < NS; jj += 32) mx = fmaxf(mx, sp[wid][jj]);
#pragma unroll
        for (int o = 16; o; o >>= 1) mx = fmaxf(mx, __shfl_xor_sync(0xffffffffu, mx, o));
        float sum = 0.f;
        for (int jj = lane; jj < NS; jj += 32) {
            float e = __expf(sp[wid][jj] - mx);
            sp[wid][jj] = e;
            sum += e;
        }
#pragma unroll
        for (int o = 16; o; o >>= 1) sum += __shfl_xor_sync(0xffffffffu, sum, o);
        float inv = 1.f / sum;
        float* Sp = S + ((size_t)b*NS + i0 + wid) * NS;
        for (int jj = lane; jj < NS; jj += 32) Sp[jj] = sp[wid][jj] * inv;
    }
}

// ---------------- av_gemm: Y[b] = S[b] @ X[b] + X[b] ----------------
// per batch M=256, N=1280, K=256. grid (2, 20, 4).
__global__ __launch_bounds__(256, 2)
void av_gemm(const float* __restrict__ S, const float* __restrict__ X,
             float* __restrict__ Y) {
    __shared__ __align__(16) float As[2*SM_A];
    __shared__ __align__(16) float Bs[2*SM_B];
    const int tid = threadIdx.x;
    const int tx = tid & 15;
    const int ty = tid >> 4;
    const int m0 = blockIdx.x * 128;
    const int n0 = blockIdx.y * 64;
    const int b  = blockIdx.z;

    const float* A = S + (size_t)b * NS * NS;
    const float* B = X + (size_t)b * NS * NV;

    const float* Aptr = A + (size_t)(m0 + (tid >> 2)) * NS + (tid & 3) * 4;
    const float* Bptr = B + (size_t)(tid >> 4) * NV + n0 + (tid & 15) * 4;

    float acc[8][4] = {};
    gemm_body(Aptr, NS, Bptr, NV, NS/16, acc, As, Bs);

#pragma unroll
    for (int i = 0; i < 8; i++) {
        int row = m0 + ty*8 + i;
        const float4 xr = *(const float4*)&B[(size_t)row * NV + n0 + tx*4];
        float4 v = make_float4(acc[i][0] + xr.x, acc[i][1] + xr.y,
                               acc[i][2] + xr.z, acc[i][3] + xr.w);
        *(float4*)&Y[((size_t)b*NS + row) * NV + n0 + tx*4] = v;
    }
}

// ---------------- row LayerNorm: Xn = LN(Y), one warp per row ----------------
__global__ void ln_rows(const float* __restrict__ Y, float* __restrict__ Xn) {
    const int tid = threadIdx.x;
    const int wid = tid >> 5, lane = tid & 31;
    const int row = blockIdx.x * 8 + wid;

    const float* yp = Y + (size_t)row * NV;
    float4 v[10];
    float s1 = 0.f, s2 = 0.f;
#pragma unroll
    for (int w = 0; w < 10; w++) {
        v[w] = *(const float4*)(yp + w*128 + lane*4);
        s1 += v[w].x + v[w].y + v[w].z + v[w].w;
        s2 += v[w].x*v[w].x + v[w].y*v[w].y + v[w].z*v[w].z + v[w].w*v[w].w;
    }
#pragma unroll
    for (int o = 16; o; o >>= 1) {
        s1 += __shfl_xor_sync(0xffffffffu, s1, o);
        s2 += __shfl_xor_sync(0xffffffffu, s2, o);
    }
    float mean = s1 * (1.f / NV);
    float var  = s2 * (1.f / NV) - mean*mean;
    float rstd = rsqrtf(var + EPSV);

    float* op = Xn + (size_t)row * NV;
#pragma unroll
    for (int w = 0; w < 10; w++) {
        float4 r;
        r.x = (v[w].x - mean) * rstd;
        r.y = (v[w].y - mean) * rstd;
        r.z = (v[w].z - mean) * rstd;
        r.w = (v[w].w - mean) * rstd;
        *(float4*)(op + w*128 + lane*4) = r;
    }
}

// ---------------- fc2_gemm: X2 = h @ W2 + b2 + Xn ----------------
// M=1024, N=1280, K=128. grid (8, 20).
__global__ __launch_bounds__(256, 2)
void fc2_gemm(const float* __restrict__ h, const float* __restrict__ W2,
              const float* __restrict__ b2, const float* __restrict__ Xn,
              float* __restrict__ X2) {
    __shared__ __align__(16) float As[2*SM_A];
    __shared__ __align__(16) float Bs[2*SM_B];
    const int tid = threadIdx.x;
    const int tx = tid & 15;
    const int ty = tid >> 4;
    const int m0 = blockIdx.x * 128;
    const int n0 = blockIdx.y * 64;

    const float* Aptr = h  + (size_t)(m0 + (tid >> 2)) * NH + (tid & 3) * 4;
    const float* Bptr = W2 + (size_t)(tid >> 4) * NV + n0 + (tid & 15) * 4;

    float acc[8][4] = {};
    gemm_body(Aptr, NH, Bptr, NV, NH/16, acc, As, Bs);

    const float4 bias = *(const float4*)&b2[n0 + tx*4];
#pragma unroll
    for (int i = 0; i < 8; i++) {
        int row = m0 + ty*8 + i;
        const float4 xr = *(const float4*)&Xn[(size_t)row * NV + n0 + tx*4];
        float4 v = make_float4(acc[i][0] + bias.x + xr.x, acc[i][1] + bias.y + xr.y,
                               acc[i][2] + bias.z + xr.z, acc[i][3] + bias.w + xr.w);
        *(float4*)&X2[(size_t)row * NV + n0 + tx*4] = v;
    }
}

// ---------------- final: lys-row attention + LN + head MLP ----------------
__global__ void final_kernel(const float* __restrict__ X, const float* __restrict__ k4T,
                             const float* __restrict__ Wq4, const float* __restrict__ wv4,
                             const int* __restrict__ lys_pos,
                             const float* __restrict__ hW1, const float* __restrict__ hb1,
                             const float* __restrict__ hW2, const float* __restrict__ hb2,
                             const float* __restrict__ hW3, const float* __restrict__ hb3,
                             float* __restrict__ out) {
    __shared__ float xl[NV];
    __shared__ float q4[NH];
    __shared__ float sp[NS];
    __shared__ float swv[NH];
    __shared__ float red[32];
    __shared__ float h1s[32];
    __shared__ float h2s[12];
    __shared__ float stats[2];

    const int b = blockIdx.x, tid = threadIdx.x;
    const int wid = tid >> 5, lane = tid & 31;
    const int lp = *lys_pos;

    const float* xrow = X + (size_t)(b*NS + lp) * NV;
    for (int v = tid; v < NV; v += 256) xl[v] = xrow[v];
    if (tid < NH) swv[tid] = wv4[tid];
    __syncthreads();

    if (tid < NH) {
        float s = 0.f;
        for (int v = 0; v < NV; v++) s += xl[v] * Wq4[(size_t)v * NH + tid];
        q4[tid] = s;
    }
    __syncthreads();

    {
        float s = 0.f;
        const float* kp = k4T + (size_t)(b*NH) * NS + tid;
        for (int h = 0; h < NH; h++) s += swv[h] * tanh_fast(q4[h] + kp[(size_t)h * NS]);
        sp[tid] = s;
    }
    __syncthreads();

    float sv = sp[tid];
    float m = sv;
#pragma unroll
    for (int o = 16; o; o >>= 1) m = fmaxf(m, __shfl_xor_sync(0xffffffffu, m, o));
    if (lane == 0) red[wid] = m;
    __syncthreads();
    if (tid == 0) {
        float t = red[0];
        for (int w = 1; w < 8; w++) t = fmaxf(t, red[w]);
        red[8] = t;
    }
    __syncthreads();
    m = red[8];
    float e = __expf(sv - m);
    float ssum = e;
#pragma unroll
    for (int o = 16; o; o >>= 1) ssum += __shfl_xor_sync(0xffffffffu, ssum, o);
    if (lane == 0) red[16 + wid] = ssum;
    __syncthreads();
    if (tid == 0) {
        float t = 0.f;
        for (int w = 0; w < 8; w++) t += red[16 + w];
        red[24] = 1.f / t;
    }
    __syncthreads();
    sp[tid] = e * red[24];
    __syncthreads();

    float4 o4 = make_float4(xl[tid*4], xl[tid*4+1], xl[tid*4+2], xl[tid*4+3]);
    float o1 = xl[1024 + tid];
    for (int jj = 0; jj < NS; jj++) {
        const float* xp = X + (size_t)(b*NS + jj) * NV;
        float4 xv = *(const float4*)(xp + tid*4);
        float pj = sp[jj];
        o4.x += pj*xv.x; o4.y += pj*xv.y; o4.z += pj*xv.z; o4.w += pj*xv.w;
        o1 += pj*xp[1024 + tid];
    }

    float s1 = o4.x + o4.y + o4.z + o4.w + o1;
    float s2 = o4.x*o4.x + o4.y*o4.y + o4.z*o4.z + o4.w*o4.w + o1*o1;
#pragma unroll
    for (int of = 16; of; of >>= 1) {
        s1 += __shfl_xor_sync(0xffffffffu, s1, of);
        s2 += __shfl_xor_sync(0xffffffffu, s2, of);
    }
    if (lane == 0) { red[wid] = s1; red[8 + wid] = s2; }
    __syncthreads();
    if (tid == 0) {
        float a = 0.f, bsq = 0.f;
        for (int w = 0; w < 8; w++) { a += red[w]; bsq += red[8 + w]; }
        float mean = a * (1.f / NV);
        float var  = bsq * (1.f / NV) - mean*mean;
        stats[0] = mean;
        stats[1] = rsqrtf(var + EPSV);
    }
    __syncthreads();
    {
        float mean = stats[0], rstd = stats[1];
        xl[tid*4+0] = (o4.x - mean) * rstd;
        xl[tid*4+1] = (o4.y - mean) * rstd;
        xl[tid*4+2] = (o4.z - mean) * rstd;
        xl[tid*4+3] = (o4.w - mean) * rstd;
        xl[1024 + tid] = (o1 - mean) * rstd;
    }
    __syncthreads();

    if (tid < 32) {
        float s = hb1[tid];
        for (int v = 0; v < NV; v++) s += xl[v] * hW1[(size_t)v * 32 + tid];
        h1s[tid] = fmaxf(s, 0.f);
    }
    __syncthreads();
    if (tid < 12) {
        float s = hb2[tid];
        for (int u = 0; u < 32; u++) s += h1s[u] * hW2[u*12 + tid];
        h2s[tid] = fmaxf(s, 0.f);
    }
    __syncthreads();
    if (tid < 2) {
        float s = hb3[tid];
        for (int u = 0; u < 12; u++) s += h2s[u] * hW3[u*2 + tid];
        out[b*2 + tid] = s;
    }
}

// ---------------- launch ----------------
extern "C" void kernel_launch(void* const* d_in, const int* in_sizes, int n_in,
                              void* d_out, int out_size) {
    const float* X   = (const float*)d_in[0];
    const int*   lys = (const int*)  d_in[1];
    const float* Wq[4]  = {(const float*)d_in[2],  (const float*)d_in[5],
                           (const float*)d_in[8],  (const float*)d_in[11]};
    const float* Wk[4]  = {(const float*)d_in[3],  (const float*)d_in[6],
                           (const float*)d_in[9],  (const float*)d_in[12]};
    const float* wv[4]  = {(const float*)d_in[4],  (const float*)d_in[7],
                           (const float*)d_in[10], (const float*)d_in[13]};
    const float* rW1[3] = {(const float*)d_in[14], (const float*)d_in[18], (const float*)d_in[22]};
    const float* rb1[3] = {(const float*)d_in[15], (const float*)d_in[19], (const float*)d_in[23]};
    const float* rW2[3] = {(const float*)d_in[16], (const float*)d_in[20], (const float*)d_in[24]};
    const float* rb2[3] = {(const float*)d_in[17], (const float*)d_in[21], (const float*)d_in[25]};
    const float* hW1 = (const float*)d_in[26];
    const float* hb1 = (const float*)d_in[27];
    const float* hW2 = (const float*)d_in[28];
    const float* hb2 = (const float*)d_in[29];
    const float* hW3 = (const float*)d_in[30];
    const float* hb3 = (const float*)d_in[31];
    float* out = (float*)d_out;

    float *q, *kT, *Xn, *h, *X2, *Y, *S, *P;
    cudaGetSymbolAddress((void**)&q,  g_q);
    cudaGetSymbolAddress((void**)&kT, g_kT);
    cudaGetSymbolAddress((void**)&Xn, g_Xn);
    cudaGetSymbolAddress((void**)&h,  g_h);
    cudaGetSymbolAddress((void**)&X2, g_X2);
    cudaGetSymbolAddress((void**)&Y,  g_Y);
    cudaGetSymbolAddress((void**)&S,  g_S);
    cudaGetSymbolAddress((void**)&P,  g_P);

    const float* cur = X;
    for (int l = 0; l < 3; l++) {
        gemm_splitk<2><<<dim3(8, 4, SPLITS), 256>>>(cur, Wq[l], Wk[l], P);
        epi_qk<<<256, 256>>>(P, q, kT);
        score_softmax<<<NROWS/8, 256>>>(q, kT, wv[l], S);
        av_gemm<<<dim3(2, 20, NB), 256>>>(S, cur, Y);
        ln_rows<<<NROWS/8, 256>>>(Y, Xn);
        gemm_splitk<1><<<dim3(8, 2, SPLITS), 256>>>(Xn, rW1[l], nullptr, P);
        epi_bias_relu<<<128, 256>>>(P, rb1[l], h);
        fc2_gemm<<<dim3(8, 20), 256>>>(h, rW2[l], rb2[l], Xn, X2);
        cur = X2;
    }
    gemm_splitk<1><<<dim3(8, 2, SPLITS), 256>>>(cur, Wk[3], nullptr, P);
    epi_ktrans<<<128, 256>>>(P, kT);
    final_kernel<<<NB, 256>>>(cur, kT, Wq[3], wv[3], lys,
                              hW1, hb1, hW2, hb2, hW3, hb3, out);
}

// round 17
// speedup vs baseline: 1.0707x; 1.0707x over previous
#include <cuda_runtime.h>
#include <math.h>

#define NB 4
#define NS 256
#define NV 1280
#define NH 128
#define EPSV 1e-5f
#define NROWS (NB*NS)        // 1024

// ---------------- scratch (no allocation allowed) ----------------
__device__ float g_q [NB*NS*NH];
__device__ float g_kT[NB*NH*NS];
__device__ float g_Xn[NB*NS*NV];
__device__ float g_h [NB*NS*NH];
__device__ float g_X2[NB*NS*NV];
__device__ float g_S [NB*NS*NS];               // softmax probabilities
__device__ float g_P [2*NROWS*NV];             // partials: 2.62M floats (fits all uses)

// single-MUFU tanh (MUFU.TANH)
__device__ __forceinline__ float tanh_fast(float x) {
    float y;
    asm("tanh.approx.f32 %0, %1;" : "=f"(y) : "f"(x));
    return y;
}

// =====================================================================
// Shared GEMM core: BM=128, BN=64, BK=16, 256 threads, 8x4 per thread.
// Double-buffered smem, one __syncthreads per k-tile, reg prefetch.
// =====================================================================
#define AS_STR 132
#define BS_STR 68
#define SM_A (16*AS_STR)
#define SM_B (16*BS_STR)

__device__ __forceinline__ void gemm_body(
    const float* __restrict__ Aptr, int lda,
    const float* __restrict__ Bptr, int ldb,
    int ntiles, float (&acc)[8][4],
    float* __restrict__ As, float* __restrict__ Bs)
{
    const int tid = threadIdx.x;
    const int tx = tid & 15;        // n group (x4)
    const int ty = tid >> 4;        // m group (x8)
    const int a_kc = tid & 3;       // k group of 4
    const int a_m  = tid >> 2;      // 0..63

    float4 ra0 = *(const float4*)Aptr;
    float4 ra1 = *(const float4*)(Aptr + (size_t)64 * lda);
    float4 rb  = *(const float4*)Bptr;

    for (int t = 0; t < ntiles; t++) {
        const int buf = t & 1;
        float* Ab = As + buf * SM_A;
        float* Bb = Bs + buf * SM_B;
        Ab[(a_kc*4+0)*AS_STR + a_m] = ra0.x;
        Ab[(a_kc*4+1)*AS_STR + a_m] = ra0.y;
        Ab[(a_kc*4+2)*AS_STR + a_m] = ra0.z;
        Ab[(a_kc*4+3)*AS_STR + a_m] = ra0.w;
        Ab[(a_kc*4+0)*AS_STR + a_m + 64] = ra1.x;
        Ab[(a_kc*4+1)*AS_STR + a_m + 64] = ra1.y;
        Ab[(a_kc*4+2)*AS_STR + a_m + 64] = ra1.z;
        Ab[(a_kc*4+3)*AS_STR + a_m + 64] = ra1.w;
        *(float4*)&Bb[(tid >> 4)*BS_STR + (tid & 15)*4] = rb;
        __syncthreads();

        if (t + 1 < ntiles) {
            const float* An = Aptr + (t+1)*16;
            const float* Bn = Bptr + (size_t)(t+1)*16*ldb;
            ra0 = *(const float4*)An;
            ra1 = *(const float4*)(An + (size_t)64 * lda);
            rb  = *(const float4*)Bn;
        }

#pragma unroll
        for (int kk = 0; kk < 16; kk++) {
            float4 a0 = *(const float4*)&Ab[kk*AS_STR + ty*8];
            float4 a1 = *(const float4*)&Ab[kk*AS_STR + ty*8 + 4];
            float4 bv = *(const float4*)&Bb[kk*BS_STR + tx*4];
            float am[8] = {a0.x,a0.y,a0.z,a0.w,a1.x,a1.y,a1.z,a1.w};
#pragma unroll
            for (int i = 0; i < 8; i++) {
                acc[i][0] += am[i]*bv.x; acc[i][1] += am[i]*bv.y;
                acc[i][2] += am[i]*bv.z; acc[i][3] += am[i]*bv.w;
            }
        }
    }
}

// ---------------- split-K SGEMM: P[s] = A[:, sK:(s+1)K] @ W_chunk ----------------
// NW=2: cols 0..127 from W0, 128..255 from W1 (fused q/k projection).
// SPL: number of K splits (KCHUNK = NV/SPL).
template<int NW, int SPL>
__global__ __launch_bounds__(256, 2)
void gemm_splitk(const float* __restrict__ A,
                 const float* __restrict__ W0,
                 const float* __restrict__ W1,
                 float* __restrict__ P) {
    __shared__ __align__(16) float As[2*SM_A];
    __shared__ __align__(16) float Bs[2*SM_B];
    const int KCH = NV / SPL;
    const int tid = threadIdx.x;
    const int tx = tid & 15;
    const int ty = tid >> 4;
    const int m0 = blockIdx.x * 128;
    const int n0 = blockIdx.y * 64;
    const int s  = blockIdx.z;
    const int kbase = s * KCH;
    const int N = NW * 128;

    const float* W = (NW == 2 && n0 >= 128) ? W1 : W0;
    const int nw0  = (NW == 2) ? (n0 & 127) : n0;

    const float* Aptr = A + (size_t)(m0 + (tid >> 2)) * NV + kbase + (tid & 3) * 4;
    const float* Bptr = W + (size_t)(kbase + (tid >> 4)) * 128 + nw0 + (tid & 15) * 4;

    float acc[8][4] = {};
    gemm_body(Aptr, NV, Bptr, 128, KCH/16, acc, As, Bs);

#pragma unroll
    for (int i = 0; i < 8; i++) {
        int m = m0 + ty*8 + i;
        float4 v = make_float4(acc[i][0], acc[i][1], acc[i][2], acc[i][3]);
        *(float4*)&P[((size_t)s * NROWS + m) * N + n0 + tx*4] = v;
    }
}

// ---- epilogue qk (10 splits): n<128 -> q, n>=128 -> kT (transposed) ----
__global__ void epi_qk(const float* __restrict__ P, float* __restrict__ q,
                       float* __restrict__ kT) {
    int gid = blockIdx.x * 256 + threadIdx.x;
    int m = gid >> 6, n = (gid & 63) * 4;
    float4 v = make_float4(0.f, 0.f, 0.f, 0.f);
#pragma unroll
    for (int s = 0; s < 10; s++) {
        float4 p = *(const float4*)&P[((size_t)s * NROWS + m) * 256 + n];
        v.x += p.x; v.y += p.y; v.z += p.z; v.w += p.w;
    }
    if (n < 128) {
        *(float4*)&q[(size_t)m * NH + n] = v;
    } else {
        int b = m >> 8, col = m & 255;
        int h = n - 128;
        kT[((size_t)(b*NH + h+0)) * NS + col] = v.x;
        kT[((size_t)(b*NH + h+1)) * NS + col] = v.y;
        kT[((size_t)(b*NH + h+2)) * NS + col] = v.z;
        kT[((size_t)(b*NH + h+3)) * NS + col] = v.w;
    }
}

// ---- epilogue fc1 (20 splits): sum + bias + relu ----
__global__ void epi_bias_relu(const float* __restrict__ P, const float* __restrict__ bias,
                              float* __restrict__ outp) {
    int gid = blockIdx.x * 256 + threadIdx.x;
    int m = gid >> 5, n = (gid & 31) * 4;
    float4 v = *(const float4*)&bias[n];
#pragma unroll
    for (int s = 0; s < 20; s++) {
        float4 p = *(const float4*)&P[((size_t)s * NROWS + m) * 128 + n];
        v.x += p.x; v.y += p.y; v.z += p.z; v.w += p.w;
    }
    v.x = fmaxf(v.x, 0.f); v.y = fmaxf(v.y, 0.f);
    v.z = fmaxf(v.z, 0.f); v.w = fmaxf(v.w, 0.f);
    *(float4*)&outp[(size_t)m * NH + n] = v;
}

// ---- epilogue k4 (20 splits): sum + transposed store ----
__global__ void epi_ktrans(const float* __restrict__ P, float* __restrict__ kT) {
    int gid = blockIdx.x * 256 + threadIdx.x;
    int m = gid >> 5, n = (gid & 31) * 4;
    float4 v = make_float4(0.f, 0.f, 0.f, 0.f);
#pragma unroll
    for (int s = 0; s < 20; s++) {
        float4 p = *(const float4*)&P[((size_t)s * NROWS + m) * 128 + n];
        v.x += p.x; v.y += p.y; v.z += p.z; v.w += p.w;
    }
    int b = m >> 8, col = m & 255;
    kT[((size_t)(b*NH + n+0)) * NS + col] = v.x;
    kT[((size_t)(b*NH + n+1)) * NS + col] = v.y;
    kT[((size_t)(b*NH + n+2)) * NS + col] = v.z;
    kT[((size_t)(b*NH + n+3)) * NS + col] = v.w;
}

// ---------------- scores + softmax -> S[b,i,j] ----------------
// G=4 rows/block -> 256 blocks.
__global__ void score_softmax(const float* __restrict__ q, const float* __restrict__ kT,
                              const float* __restrict__ wv, float* __restrict__ S) {
    const int G = 4;
    __shared__ float sq[G][NH];
    __shared__ float swv[NH];
    __shared__ float sp[G][NS];

    const int tid = threadIdx.x;
    const int b  = blockIdx.x >> 6;           // 64 blocks per batch
    const int i0 = (blockIdx.x & 63) * G;
    const int wid = tid >> 5, lane = tid & 31;

    if (tid < NH) swv[tid] = wv[tid];
    for (int t = tid; t < G*NH; t += 256) {
        int r = t >> 7, h = t & 127;
        sq[r][h] = q[(size_t)(b*NS + i0 + r) * NH + h];
    }
    __syncthreads();

    {
        float sc[G];
#pragma unroll
        for (int r = 0; r < G; r++) sc[r] = 0.f;
        const float* kp = kT + (size_t)(b*NH) * NS + tid;
        for (int h = 0; h < NH; h++) {
            float kv = kp[(size_t)h * NS];
            float w  = swv[h];
#pragma unroll
            for (int r = 0; r < G; r++) sc[r] += w * tanh_fast(sq[r][h] + kv);
        }
#pragma unroll
        for (int r = 0; r < G; r++) sp[r][tid] = sc[r];
    }
    __syncthreads();

    if (wid < G) {
        float mx = -1e30f;
        for (int jj = lane; jj < NS; jj += 32) mx = fmaxf(mx, sp[wid][jj]);
#pragma unroll
        for (int o = 16; o; o >>= 1) mx = fmaxf(mx, __shfl_xor_sync(0xffffffffu, mx, o));
        float sum = 0.f;
        for (int jj = lane; jj < NS; jj += 32) {
            float e = __expf(sp[wid][jj] - mx);
            sp[wid][jj] = e;
            sum += e;
        }
#pragma unroll
        for (int o = 16; o; o >>= 1) sum += __shfl_xor_sync(0xffffffffu, sum, o);
        float inv = 1.f / sum;
        float* Sp = S + ((size_t)b*NS + i0 + wid) * NS;
        for (int jj = lane; jj < NS; jj += 32) Sp[jj] = sp[wid][jj] * inv;
    }
}

// ---------------- av_gemm split-K: P[s] partial of S[b] @ X[b] ----------------
// K=256 split into 2x128. grid (2, 20, 8) z = b*2+s.
__global__ __launch_bounds__(256, 2)
void av_gemm_sk(const float* __restrict__ S, const float* __restrict__ X,
                float* __restrict__ P) {
    __shared__ __align__(16) float As[2*SM_A];
    __shared__ __align__(16) float Bs[2*SM_B];
    const int tid = threadIdx.x;
    const int tx = tid & 15;
    const int ty = tid >> 4;
    const int m0 = blockIdx.x * 128;
    const int n0 = blockIdx.y * 64;
    const int b  = blockIdx.z >> 1;
    const int s  = blockIdx.z & 1;
    const int kbase = s * 128;

    const float* A = S + (size_t)b * NS * NS;
    const float* B = X + (size_t)b * NS * NV;

    const float* Aptr = A + (size_t)(m0 + (tid >> 2)) * NS + kbase + (tid & 3) * 4;
    const float* Bptr = B + (size_t)(kbase + (tid >> 4)) * NV + n0 + (tid & 15) * 4;

    float acc[8][4] = {};
    gemm_body(Aptr, NS, Bptr, NV, 8, acc, As, Bs);

#pragma unroll
    for (int i = 0; i < 8; i++) {
        int row = m0 + ty*8 + i;
        float4 v = make_float4(acc[i][0], acc[i][1], acc[i][2], acc[i][3]);
        *(float4*)&P[((size_t)(s*NROWS) + b*NS + row) * NV + n0 + tx*4] = v;
    }
}

// ---------------- ln_rows: Xn = LN(P0 + P1 + X), one warp per row ----------------
__global__ void ln_rows(const float* __restrict__ P, const float* __restrict__ X,
                        float* __restrict__ Xn) {
    const int tid = threadIdx.x;
    const int wid = tid >> 5, lane = tid & 31;
    const int row = blockIdx.x * 8 + wid;

    const float* p0 = P + (size_t)row * NV;
    const float* p1 = P + (size_t)(NROWS + row) * NV;
    const float* xp = X + (size_t)row * NV;
    float4 v[10];
    float s1 = 0.f, s2 = 0.f;
#pragma unroll
    for (int w = 0; w < 10; w++) {
        float4 a = *(const float4*)(p0 + w*128 + lane*4);
        float4 bq = *(const float4*)(p1 + w*128 + lane*4);
        float4 x = *(const float4*)(xp + w*128 + lane*4);
        v[w].x = a.x + bq.x + x.x;
        v[w].y = a.y + bq.y + x.y;
        v[w].z = a.z + bq.z + x.z;
        v[w].w = a.w + bq.w + x.w;
        s1 += v[w].x + v[w].y + v[w].z + v[w].w;
        s2 += v[w].x*v[w].x + v[w].y*v[w].y + v[w].z*v[w].z + v[w].w*v[w].w;
    }
#pragma unroll
    for (int o = 16; o; o >>= 1) {
        s1 += __shfl_xor_sync(0xffffffffu, s1, o);
        s2 += __shfl_xor_sync(0xffffffffu, s2, o);
    }
    float mean = s1 * (1.f / NV);
    float var  = s2 * (1.f / NV) - mean*mean;
    float rstd = rsqrtf(var + EPSV);

    float* op = Xn + (size_t)row * NV;
#pragma unroll
    for (int w = 0; w < 10; w++) {
        float4 r;
        r.x = (v[w].x - mean) * rstd;
        r.y = (v[w].y - mean) * rstd;
        r.z = (v[w].z - mean) * rstd;
        r.w = (v[w].w - mean) * rstd;
        *(float4*)(op + w*128 + lane*4) = r;
    }
}

// ---------------- fc2 split-K: P[s] partial of h @ W2 ----------------
// K=128 split into 2x64. grid (8, 20, 2).
__global__ __launch_bounds__(256, 2)
void fc2_sk(const float* __restrict__ h, const float* __restrict__ W2,
            float* __restrict__ P) {
    __shared__ __align__(16) float As[2*SM_A];
    __shared__ __align__(16) float Bs[2*SM_B];
    const int tid = threadIdx.x;
    const int tx = tid & 15;
    const int ty = tid >> 4;
    const int m0 = blockIdx.x * 128;
    const int n0 = blockIdx.y * 64;
    const int s  = blockIdx.z;
    const int kbase = s * 64;

    const float* Aptr = h  + (size_t)(m0 + (tid >> 2)) * NH + kbase + (tid & 3) * 4;
    const float* Bptr = W2 + (size_t)(kbase + (tid >> 4)) * NV + n0 + (tid & 15) * 4;

    float acc[8][4] = {};
    gemm_body(Aptr, NH, Bptr, NV, 4, acc, As, Bs);

#pragma unroll
    for (int i = 0; i < 8; i++) {
        int row = m0 + ty*8 + i;
        float4 v = make_float4(acc[i][0], acc[i][1], acc[i][2], acc[i][3]);
        *(float4*)&P[((size_t)(s*NROWS) + row) * NV + n0 + tx*4] = v;
    }
}

// ---- epilogue fc2: X2 = P0 + P1 + b2 + Xn ----
__global__ void epi_fc2(const float* __restrict__ P, const float* __restrict__ b2,
                        const float* __restrict__ Xn, float* __restrict__ X2) {
    int idx = blockIdx.x * 256 + threadIdx.x;     // over 1024*320
    int m = idx / 320;
    int c = (idx - m * 320) * 4;
    float4 a = *(const float4*)&P[(size_t)m * NV + c];
    float4 bq = *(const float4*)&P[(size_t)(NROWS + m) * NV + c];
    float4 bb = *(const float4*)&b2[c];
    float4 x = *(const float4*)&Xn[(size_t)m * NV + c];
    float4 v = make_float4(a.x + bq.x + bb.x + x.x, a.y + bq.y + bb.y + x.y,
                           a.z + bq.z + bb.z + x.z, a.w + bq.w + bb.w + x.w);
    *(float4*)&X2[(size_t)m * NV + c] = v;
}

// ---------------- final: lys-row attention + LN + head MLP ----------------
__global__ void final_kernel(const float* __restrict__ X, const float* __restrict__ k4T,
                             const float* __restrict__ Wq4, const float* __restrict__ wv4,
                             const int* __restrict__ lys_pos,
                             const float* __restrict__ hW1, const float* __restrict__ hb1,
                             const float* __restrict__ hW2, const float* __restrict__ hb2,
                             const float* __restrict__ hW3, const float* __restrict__ hb3,
                             float* __restrict__ out) {
    __shared__ float xl[NV];
    __shared__ float q4[NH];
    __shared__ float sp[NS];
    __shared__ float swv[NH];
    __shared__ float red[32];
    __shared__ float h1s[32];
    __shared__ float h2s[12];
    __shared__ float stats[2];

    const int b = blockIdx.x, tid = threadIdx.x;
    const int wid = tid >> 5, lane = tid & 31;
    const int lp = *lys_pos;

    const float* xrow = X + (size_t)(b*NS + lp) * NV;
    for (int v = tid; v < NV; v += 256) xl[v] = xrow[v];
    if (tid < NH) swv[tid] = wv4[tid];
    __syncthreads();

    if (tid < NH) {
        float s = 0.f;
        for (int v = 0; v < NV; v++) s += xl[v] * Wq4[(size_t)v * NH + tid];
        q4[tid] = s;
    }
    __syncthreads();

    {
        float s = 0.f;
        const float* kp = k4T + (size_t)(b*NH) * NS + tid;
        for (int h = 0; h < NH; h++) s += swv[h] * tanh_fast(q4[h] + kp[(size_t)h * NS]);
        sp[tid] = s;
    }
    __syncthreads();

    float sv = sp[tid];
    float m = sv;
#pragma unroll
    for (int o = 16; o; o >>= 1) m = fmaxf(m, __shfl_xor_sync(0xffffffffu, m, o));
    if (lane == 0) red[wid] = m;
    __syncthreads();
    if (tid == 0) {
        float t = red[0];
        for (int w = 1; w < 8; w++) t = fmaxf(t, red[w]);
        red[8] = t;
    }
    __syncthreads();
    m = red[8];
    float e = __expf(sv - m);
    float ssum = e;
#pragma unroll
    for (int o = 16; o; o >>= 1) ssum += __shfl_xor_sync(0xffffffffu, ssum, o);
    if (lane == 0) red[16 + wid] = ssum;
    __syncthreads();
    if (tid == 0) {
        float t = 0.f;
        for (int w = 0; w < 8; w++) t += red[16 + w];
        red[24] = 1.f / t;
    }
    __syncthreads();
    sp[tid] = e * red[24];
    __syncthreads();

    float4 o4 = make_float4(xl[tid*4], xl[tid*4+1], xl[tid*4+2], xl[tid*4+3]);
    float o1 = xl[1024 + tid];
    for (int jj = 0; jj < NS; jj++) {
        const float* xp = X + (size_t)(b*NS + jj) * NV;
        float4 xv = *(const float4*)(xp + tid*4);
        float pj = sp[jj];
        o4.x += pj*xv.x; o4.y += pj*xv.y; o4.z += pj*xv.z; o4.w += pj*xv.w;
        o1 += pj*xp[1024 + tid];
    }

    float s1 = o4.x + o4.y + o4.z + o4.w + o1;
    float s2 = o4.x*o4.x + o4.y*o4.y + o4.z*o4.z + o4.w*o4.w + o1*o1;
#pragma unroll
    for (int of = 16; of; of >>= 1) {
        s1 += __shfl_xor_sync(0xffffffffu, s1, of);
        s2 += __shfl_xor_sync(0xffffffffu, s2, of);
    }
    if (lane == 0) { red[wid] = s1; red[8 + wid] = s2; }
    __syncthreads();
    if (tid == 0) {
        float a = 0.f, bsq = 0.f;
        for (int w = 0; w < 8; w++) { a += red[w]; bsq += red[8 + w]; }
        float mean = a * (1.f / NV);
        float var  = bsq * (1.f / NV) - mean*mean;
        stats[0] = mean;
        stats[1] = rsqrtf(var + EPSV);
    }
    __syncthreads();
    {
        float mean = stats[0], rstd = stats[1];
        xl[tid*4+0] = (o4.x - mean) * rstd;
        xl[tid*4+1] = (o4.y - mean) * rstd;
        xl[tid*4+2] = (o4.z - mean) * rstd;
        xl[tid*4+3] = (o4.w - mean) * rstd;
        xl[1024 + tid] = (o1 - mean) * rstd;
    }
    __syncthreads();

    if (tid < 32) {
        float s = hb1[tid];
        for (int v = 0; v < NV; v++) s += xl[v] * hW1[(size_t)v * 32 + tid];
        h1s[tid] = fmaxf(s, 0.f);
    }
    __syncthreads();
    if (tid < 12) {
        float s = hb2[tid];
        for (int u = 0; u < 32; u++) s += h1s[u] * hW2[u*12 + tid];
        h2s[tid] = fmaxf(s, 0.f);
    }
    __syncthreads();
    if (tid < 2) {
        float s = hb3[tid];
        for (int u = 0; u < 12; u++) s += h2s[u] * hW3[u*2 + tid];
        out[b*2 + tid] = s;
    }
}

// ---------------- launch ----------------
extern "C" void kernel_launch(void* const* d_in, const int* in_sizes, int n_in,
                              void* d_out, int out_size) {
    const float* X   = (const float*)d_in[0];
    const int*   lys = (const int*)  d_in[1];
    const float* Wq[4]  = {(const float*)d_in[2],  (const float*)d_in[5],
                           (const float*)d_in[8],  (const float*)d_in[11]};
    const float* Wk[4]  = {(const float*)d_in[3],  (const float*)d_in[6],
                           (const float*)d_in[9],  (const float*)d_in[12]};
    const float* wv[4]  = {(const float*)d_in[4],  (const float*)d_in[7],
                           (const float*)d_in[10], (const float*)d_in[13]};
    const float* rW1[3] = {(const float*)d_in[14], (const float*)d_in[18], (const float*)d_in[22]};
    const float* rb1[3] = {(const float*)d_in[15], (const float*)d_in[19], (const float*)d_in[23]};
    const float* rW2[3] = {(const float*)d_in[16], (const float*)d_in[20], (const float*)d_in[24]};
    const float* rb2[3] = {(const float*)d_in[17], (const float*)d_in[21], (const float*)d_in[25]};
    const float* hW1 = (const float*)d_in[26];
    const float* hb1 = (const float*)d_in[27];
    const float* hW2 = (const float*)d_in[28];
    const float* hb2 = (const float*)d_in[29];
    const float* hW3 = (const float*)d_in[30];
    const float* hb3 = (const float*)d_in[31];
    float* out = (float*)d_out;

    float *q, *kT, *Xn, *h, *X2, *S, *P;
    cudaGetSymbolAddress((void**)&q,  g_q);
    cudaGetSymbolAddress((void**)&kT, g_kT);
    cudaGetSymbolAddress((void**)&Xn, g_Xn);
    cudaGetSymbolAddress((void**)&h,  g_h);
    cudaGetSymbolAddress((void**)&X2, g_X2);
    cudaGetSymbolAddress((void**)&S,  g_S);
    cudaGetSymbolAddress((void**)&P,  g_P);

    const float* cur = X;
    for (int l = 0; l < 3; l++) {
        gemm_splitk<2, 10><<<dim3(8, 4, 10), 256>>>(cur, Wq[l], Wk[l], P);
        epi_qk<<<256, 256>>>(P, q, kT);
        score_softmax<<<256, 256>>>(q, kT, wv[l], S);
        av_gemm_sk<<<dim3(2, 20, 8), 256>>>(S, cur, P);
        ln_rows<<<128, 256>>>(P, cur, Xn);
        gemm_splitk<1, 20><<<dim3(8, 2, 20), 256>>>(Xn, rW1[l], nullptr, P);
        epi_bias_relu<<<128, 256>>>(P, rb1[l], h);
        fc2_sk<<<dim3(8, 20, 2), 256>>>(h, rW2[l], P);
        epi_fc2<<<1280, 256>>>(P, rb2[l], Xn, X2);
        cur = X2;
    }
    gemm_splitk<1, 20><<<dim3(8, 2, 20), 256>>>(cur, Wk[3], nullptr, P);
    epi_ktrans<<<128, 256>>>(P, kT);
    final_kernel<<<NB, 256>>>(cur, kT, Wq[3], wv[3], lys,
                              hW1, hb1, hW2, hb2, hW3, hb3, out);
}